// round 16
// baseline (speedup 1.0000x reference)
#include <cuda_runtime.h>
#include <cuda_bf16.h>
#include <cstdint>

#define cN0 200000
#define cN1 50000
#define cN2 10000
#define cL  10
#define cE0 800000
#define cE1 160000
#define cIN 128
#define cU  32
#define cLP 128

// ---------------- scratch (device globals; no runtime allocation) ----------------
__device__ float g_h0[(size_t)cN0 * 160];
__device__ __nv_bfloat16 g_h0b[(size_t)cN0 * 160];
__device__ float g_h1feat[(size_t)cN1 * 256];
__device__ float g_un0[(size_t)cN1 * 32];
__device__ float g_X0[(size_t)cN1 * 256];
__device__ float g_X1[(size_t)cN2 * 512];
__device__ float g_A[cE0];
__device__ float g_A1[cE1];
// L0 CSR
__device__ int   g_eidx[cE0];
__device__ int   g_rowptr[cN1 + 1];
__device__ int   g_deg[cN1];
__device__ int   g_cursor[cN1];
// L1 CSR
__device__ int   g_eidx1[cE1];
__device__ int   g_rowptr1[cN2 + 1];
__device__ int   g_deg1[cN2];
__device__ int   g_cursor1[cN2];
__device__ float g_W0[256 * 256];
__device__ float g_W1[512 * 256];

__device__ __forceinline__ float tf32r(float x) {
  uint32_t u;
  asm("cvt.rna.tf32.f32 %0, %1;" : "=r"(u) : "f"(x));
  return __uint_as_float(u);
}
__device__ __forceinline__ void mma_tf32(float& d0, float& d1, float& d2, float& d3,
                                         uint32_t a0, uint32_t a1, uint32_t a2, uint32_t a3,
                                         uint32_t b0, uint32_t b1) {
  asm volatile(
      "mma.sync.aligned.m16n8k8.row.col.f32.tf32.tf32.f32 "
      "{%0,%1,%2,%3}, {%4,%5,%6,%7}, {%8,%9}, {%0,%1,%2,%3};"
      : "+f"(d0), "+f"(d1), "+f"(d2), "+f"(d3)
      : "r"(a0), "r"(a1), "r"(a2), "r"(a3), "r"(b0), "r"(b1));
}
__device__ __forceinline__ void mma_bf16(float& d0, float& d1, float& d2, float& d3,
                                         uint32_t a0, uint32_t a1, uint32_t a2, uint32_t a3,
                                         uint32_t b0, uint32_t b1) {
  asm volatile(
      "mma.sync.aligned.m16n8k16.row.col.f32.bf16.bf16.f32 "
      "{%0,%1,%2,%3}, {%4,%5,%6,%7}, {%8,%9}, {%0,%1,%2,%3};"
      : "+f"(d0), "+f"(d1), "+f"(d2), "+f"(d3)
      : "r"(a0), "r"(a1), "r"(a2), "r"(a3), "r"(b0), "r"(b1));
}
__device__ __forceinline__ uint32_t pack_bf16(float lo, float hi) {
  __nv_bfloat162 p = __float22bfloat162_rn(make_float2(lo, hi));
  return *reinterpret_cast<uint32_t*>(&p);
}
__device__ __forceinline__ float2 bf2f(uint32_t u) {
  return __bfloat1622float2(*reinterpret_cast<__nv_bfloat162*>(&u));
}

// ---------------- embedding bag + LN + relu + bf16 shadow (warp per node) ----------------
__global__ void k_embed(const int* __restrict__ x, const float* __restrict__ xu,
                        const float* __restrict__ tab, const float* __restrict__ g,
                        const float* __restrict__ b) {
  int n = (blockIdx.x * blockDim.x + threadIdx.x) >> 5;
  int lane = threadIdx.x & 31;
  if (n >= cN0) return;
  const int* xr = x + (size_t)n * cL;
  float4 v = make_float4(0.f, 0.f, 0.f, 0.f);
#pragma unroll
  for (int l = 0; l < cL; l++) {
    int id = xr[l];
    if (id != 0) {
      float4 t = ((const float4*)(tab + (size_t)id * cIN))[lane];
      v.x += t.x; v.y += t.y; v.z += t.z; v.w += t.w;
    }
  }
  float s = v.x + v.y + v.z + v.w;
  float q = v.x * v.x + v.y * v.y + v.z * v.z + v.w * v.w;
#pragma unroll
  for (int o = 16; o; o >>= 1) {
    s += __shfl_xor_sync(0xffffffffu, s, o);
    q += __shfl_xor_sync(0xffffffffu, q, o);
  }
  float m = s * (1.f / cIN);
  float rs = rsqrtf(q * (1.f / cIN) - m * m + 1e-5f);
  float4 gv = ((const float4*)g)[lane];
  float4 bv = ((const float4*)b)[lane];
  float4 ov;
  ov.x = fmaxf((v.x - m) * rs * gv.x + bv.x, 0.f);
  ov.y = fmaxf((v.y - m) * rs * gv.y + bv.y, 0.f);
  ov.z = fmaxf((v.z - m) * rs * gv.z + bv.z, 0.f);
  ov.w = fmaxf((v.w - m) * rs * gv.w + bv.w, 0.f);
  if (n < cN1) ((float4*)(g_h0 + (size_t)n * 160))[lane] = ov;
  // bf16 feat shadow only (unsup handled from xu directly everywhere now)
  __nv_bfloat16* rb = g_h0b + (size_t)n * 160;
  uint2 pk;
  pk.x = pack_bf16(ov.x, ov.y);
  pk.y = pack_bf16(ov.z, ov.w);
  ((uint2*)rb)[lane] = pk;
}

// ---------------- CSR build ----------------
__global__ void k_zero_deg(int* __restrict__ deg, int n) {
  int i = blockIdx.x * blockDim.x + threadIdx.x;
  if (i < n) deg[i] = 0;
}
__global__ void k_hist(const int* __restrict__ dst, int* __restrict__ deg, int E) {
  int i = blockIdx.x * blockDim.x + threadIdx.x;
  if (i < E) atomicAdd(&deg[dst[i]], 1);
}
__global__ void k_scan(int* __restrict__ deg, int* __restrict__ rowptr,
                       int* __restrict__ cursor, int n, int E) {
  __shared__ int sh[1024];
  int t = threadIdx.x;
  int chunk = (n + 1023) / 1024;
  int beg = t * chunk;
  int end = beg + chunk; if (end > n) end = n; if (beg > n) beg = n;
  int local = 0;
  for (int i = beg; i < end; i++) local += deg[i];
  sh[t] = local;
  __syncthreads();
  for (int off = 1; off < 1024; off <<= 1) {
    int v = (t >= off) ? sh[t - off] : 0;
    __syncthreads();
    sh[t] += v;
    __syncthreads();
  }
  int offset = (t == 0) ? 0 : sh[t - 1];
  for (int i = beg; i < end; i++) {
    rowptr[i] = offset;
    cursor[i] = offset;
    offset += deg[i];
  }
  if (t == 0) rowptr[n] = E;
}
__global__ void k_scatter(const int* __restrict__ dst, int* __restrict__ cursor,
                          int* __restrict__ eidx, int E) {
  int i = blockIdx.x * blockDim.x + threadIdx.x;
  if (i < E) {
    int pos = atomicAdd(&cursor[dst[i]], 1);
    eidx[pos] = i;
  }
}

// ---------------- un0 from xu directly (fp32 exact; A-independent) ----------------
__global__ void k_aggu(const int* __restrict__ src, const int* __restrict__ rowptr,
                       const int* __restrict__ eidx, const float* __restrict__ xu) {
  int gw = (blockIdx.x * blockDim.x + threadIdx.x) >> 5;
  int lane = threadIdx.x & 31;
  if (gw >= cN1) return;
  int beg = rowptr[gw], end = rowptr[gw + 1];
  float au = 0.f;
  for (int chunk = beg; chunk < end; chunk += 32) {
    int n = end - chunk; if (n > 32) n = 32;
    int myi = chunk + lane;
    int e = (myi < end) ? eidx[myi] : 0;
    int s = (myi < end) ? src[e] : 0;
    int t = 0;
    for (; t + 1 < n; t += 2) {
      int sA = __shfl_sync(0xffffffffu, s, t);
      int sB = __shfl_sync(0xffffffffu, s, t + 1);
      float vA = xu[(size_t)sA * cU + lane];
      float vB = xu[(size_t)sB * cU + lane];
      au += vA;
      au += vB;
    }
    if (t < n) {
      int st = __shfl_sync(0xffffffffu, s, t);
      au += xu[(size_t)st * cU + lane];
    }
  }
  g_un0[(size_t)gw * 32 + lane] = au;
}

// ---------------- per-edge LP attention MLP via bf16 mma m16n8k16, single pass ----------
__global__ __launch_bounds__(256, 2)
void k_edge_lp(const int* __restrict__ src, const int* __restrict__ dst, int E,
               const float* __restrict__ usrc, int sstr, int soff,
               const float* __restrict__ utgt, int tstr, int toff,
               const float* __restrict__ w1, const float* __restrict__ b1,
               const float* __restrict__ lg, const float* __restrict__ lbn,
               const float* __restrict__ w2, const float* __restrict__ b2p,
               float* __restrict__ Aout) {
  extern __shared__ float sm[];
  uint32_t* w1b = (uint32_t*)sm;
  float4* pp = (float4*)(sm + 6656);
  uint32_t* hstage = (uint32_t*)(sm + 6656 + 512);

  for (int i = threadIdx.x; i < 128 * 48; i += blockDim.x) {
    int o = i / 48, j = i % 48;
    w1b[o * 52 + j] = pack_bf16(w1[o * 96 + 2 * j], w1[o * 96 + 2 * j + 1]);
  }
  for (int i = threadIdx.x; i < 128; i += blockDim.x)
    pp[i] = make_float4(lg[i], lbn[i], w2[i], b1[i]);
  __syncthreads();

  int lane = threadIdx.x & 31;
  int w = threadIdx.x >> 5;
  int gid = lane >> 2;
  int tig = lane & 3;
  uint32_t* myh = hstage + w * (16 * 52);
  float b2v = b2p[0];
  int warps_tot = gridDim.x * (blockDim.x >> 5);

  for (long base = ((long)blockIdx.x * (blockDim.x >> 5) + w) * 16; base < E;
       base += (long)warps_tot * 16) {
#pragma unroll
    for (int t = 0; t < 16; t++) {
      long ee = base + t;
      int e = (ee < E) ? (int)ee : (E - 1);
      int sn = src[e], dn = dst[e];
      float uj = usrc[(size_t)sn * sstr + soff + lane];
      float ui = utgt[(size_t)dn * tstr + toff + lane];
      float v0 = fabsf(ui - uj);
      float v1 = ui + uj;
      float v2 = ui * uj;
      float n0 = __shfl_down_sync(0xffffffffu, v0, 1);
      float n1 = __shfl_down_sync(0xffffffffu, v1, 1);
      float n2 = __shfl_down_sync(0xffffffffu, v2, 1);
      if ((lane & 1) == 0) {
        int j = lane >> 1;
        uint32_t* row = myh + t * 52;
        row[j]      = pack_bf16(v0, n0);
        row[16 + j] = pack_bf16(v1, n1);
        row[32 + j] = pack_bf16(v2, n2);
      }
    }
    __syncwarp();

    uint32_t A[6][4];
#pragma unroll
    for (int kk = 0; kk < 6; kk++) {
      int ko = kk * 8 + tig;
      A[kk][0] = myh[gid * 52 + ko];
      A[kk][1] = myh[(gid + 8) * 52 + ko];
      A[kk][2] = myh[gid * 52 + ko + 4];
      A[kk][3] = myh[(gid + 8) * 52 + ko + 4];
    }

    float acc[16][4];
    float S0 = 0.f, Q0 = 0.f, S1 = 0.f, Q1 = 0.f;
#pragma unroll
    for (int nn = 0; nn < 16; nn++) {
      float d0 = 0.f, d1 = 0.f, d2 = 0.f, d3 = 0.f;
      const uint32_t* wrow = w1b + (nn * 8 + gid) * 52 + tig;
#pragma unroll
      for (int kk = 0; kk < 6; kk++) {
        uint32_t b0 = wrow[kk * 8];
        uint32_t b1r = wrow[kk * 8 + 4];
        mma_bf16(d0, d1, d2, d3, A[kk][0], A[kk][1], A[kk][2], A[kk][3], b0, b1r);
      }
      float4 p0 = pp[nn * 8 + 2 * tig];
      float4 p1 = pp[nn * 8 + 2 * tig + 1];
      d0 += p0.w; d1 += p1.w; d2 += p0.w; d3 += p1.w;
      acc[nn][0] = d0; acc[nn][1] = d1; acc[nn][2] = d2; acc[nn][3] = d3;
      S0 += d0 + d1; Q0 += d0 * d0 + d1 * d1;
      S1 += d2 + d3; Q1 += d2 * d2 + d3 * d3;
    }
#pragma unroll
    for (int o = 1; o <= 2; o <<= 1) {
      S0 += __shfl_xor_sync(0xffffffffu, S0, o);
      Q0 += __shfl_xor_sync(0xffffffffu, Q0, o);
      S1 += __shfl_xor_sync(0xffffffffu, S1, o);
      Q1 += __shfl_xor_sync(0xffffffffu, Q1, o);
    }
    float m0 = S0 * (1.f / 128.f);
    float rs0 = rsqrtf(Q0 * (1.f / 128.f) - m0 * m0 + 1e-5f);
    float m1 = S1 * (1.f / 128.f);
    float rs1 = rsqrtf(Q1 * (1.f / 128.f) - m1 * m1 + 1e-5f);

    float P0 = 0.f, P1 = 0.f;
#pragma unroll
    for (int nn = 0; nn < 16; nn++) {
      float4 p0 = pp[nn * 8 + 2 * tig];
      float4 p1 = pp[nn * 8 + 2 * tig + 1];
      P0 += fmaxf((acc[nn][0] - m0) * rs0 * p0.x + p0.y, 0.f) * p0.z;
      P0 += fmaxf((acc[nn][1] - m0) * rs0 * p1.x + p1.y, 0.f) * p1.z;
      P1 += fmaxf((acc[nn][2] - m1) * rs1 * p0.x + p0.y, 0.f) * p0.z;
      P1 += fmaxf((acc[nn][3] - m1) * rs1 * p1.x + p1.y, 0.f) * p1.z;
    }
#pragma unroll
    for (int o = 1; o <= 2; o <<= 1) {
      P0 += __shfl_xor_sync(0xffffffffu, P0, o);
      P1 += __shfl_xor_sync(0xffffffffu, P1, o);
    }
    if (tig == 0) {
      if (base + gid < E)
        Aout[base + gid] = 1.f / (1.f + expf(-(P0 + b2v)));
      if (base + gid + 8 < E)
        Aout[base + gid + 8] = 1.f / (1.f + expf(-(P1 + b2v)));
    }
    __syncwarp();
  }
}

// ---------------- gather aggregation, unroll-2 prefetch (feat only) -------
__global__ void k_agg0(const int* __restrict__ src, const int* __restrict__ rowptr,
                       const int* __restrict__ eidx) {
  int gw = (blockIdx.x * blockDim.x + threadIdx.x) >> 5;
  int lane = threadIdx.x & 31;
  if (gw >= cN1) return;
  int beg = rowptr[gw], end = rowptr[gw + 1];
  float a0 = 0.f, a1 = 0.f, a2 = 0.f, a3 = 0.f;
  float asum = 0.f;
  for (int chunk = beg; chunk < end; chunk += 32) {
    int n = end - chunk; if (n > 32) n = 32;
    int myi = chunk + lane;
    int e = (myi < end) ? eidx[myi] : 0;
    int s = (myi < end) ? src[e] : 0;
    float a = (myi < end) ? g_A[e] : 0.f;
    asum += a;
    int t = 0;
    for (; t + 1 < n; t += 2) {
      int sA = __shfl_sync(0xffffffffu, s, t);
      int sB = __shfl_sync(0xffffffffu, s, t + 1);
      float aA = __shfl_sync(0xffffffffu, a, t);
      float aB = __shfl_sync(0xffffffffu, a, t + 1);
      const uint32_t* rA = (const uint32_t*)(g_h0b + (size_t)sA * 160);
      const uint32_t* rB = (const uint32_t*)(g_h0b + (size_t)sB * 160);
      uint32_t wA0 = rA[lane], wA1 = rA[32 + lane];
      uint32_t wB0 = rB[lane], wB1 = rB[32 + lane];
      float2 fA0 = bf2f(wA0), fA1 = bf2f(wA1);
      a0 = fmaf(aA, fA0.x, a0); a1 = fmaf(aA, fA0.y, a1);
      a2 = fmaf(aA, fA1.x, a2); a3 = fmaf(aA, fA1.y, a3);
      float2 fB0 = bf2f(wB0), fB1 = bf2f(wB1);
      a0 = fmaf(aB, fB0.x, a0); a1 = fmaf(aB, fB0.y, a1);
      a2 = fmaf(aB, fB1.x, a2); a3 = fmaf(aB, fB1.y, a3);
    }
    if (t < n) {
      int st = __shfl_sync(0xffffffffu, s, t);
      float at = __shfl_sync(0xffffffffu, a, t);
      const uint32_t* rp = (const uint32_t*)(g_h0b + (size_t)st * 160);
      float2 f0 = bf2f(rp[lane]);
      float2 f1 = bf2f(rp[32 + lane]);
      a0 = fmaf(at, f0.x, a0); a1 = fmaf(at, f0.y, a1);
      a2 = fmaf(at, f1.x, a2); a3 = fmaf(at, f1.y, a3);
    }
  }
#pragma unroll
  for (int o = 16; o; o >>= 1) asum += __shfl_xor_sync(0xffffffffu, asum, o);
  float inv = (end > beg) ? 1.f / asum : 0.f;
  a0 *= inv; a1 *= inv; a2 *= inv; a3 *= inv;
  float* X = g_X0 + (size_t)gw * 256;
  *(float2*)(X + 2 * lane) = make_float2(a0, a1);
  *(float2*)(X + 64 + 2 * lane) = make_float2(a2, a3);
  const float* ht = g_h0 + (size_t)gw * 160;
  X[128 + lane] = ht[lane];
  X[160 + lane] = ht[32 + lane];
  X[192 + lane] = ht[64 + lane];
  X[224 + lane] = ht[96 + lane];
}

__global__ void k_agg1(const int* __restrict__ src, const int* __restrict__ rowptr,
                       const int* __restrict__ eidx, const float* __restrict__ Aarr) {
  int gw = (blockIdx.x * blockDim.x + threadIdx.x) >> 5;
  int lane = threadIdx.x & 31;
  if (gw >= cN2) return;
  int beg = rowptr[gw], end = rowptr[gw + 1];
  float acc[8] = {0.f, 0.f, 0.f, 0.f, 0.f, 0.f, 0.f, 0.f};
  float asum = 0.f;
  for (int chunk = beg; chunk < end; chunk += 32) {
    int n = end - chunk; if (n > 32) n = 32;
    int myi = chunk + lane;
    int e = (myi < end) ? eidx[myi] : 0;
    int s = (myi < end) ? src[e] : 0;
    float a = (myi < end) ? Aarr[e] : 0.f;
    asum += a;
    int t = 0;
    for (; t + 1 < n; t += 2) {
      int sA = __shfl_sync(0xffffffffu, s, t);
      int sB = __shfl_sync(0xffffffffu, s, t + 1);
      float aA = __shfl_sync(0xffffffffu, a, t);
      float aB = __shfl_sync(0xffffffffu, a, t + 1);
      const float* rA = g_h1feat + (size_t)sA * 256;
      const float* rB = g_h1feat + (size_t)sB * 256;
      float vA[8], vB[8];
#pragma unroll
      for (int k = 0; k < 8; k++) vA[k] = rA[(k << 5) + lane];
#pragma unroll
      for (int k = 0; k < 8; k++) vB[k] = rB[(k << 5) + lane];
#pragma unroll
      for (int k = 0; k < 8; k++) acc[k] = fmaf(aA, vA[k], acc[k]);
#pragma unroll
      for (int k = 0; k < 8; k++) acc[k] = fmaf(aB, vB[k], acc[k]);
    }
    if (t < n) {
      int st = __shfl_sync(0xffffffffu, s, t);
      float at = __shfl_sync(0xffffffffu, a, t);
      const float* row = g_h1feat + (size_t)st * 256;
#pragma unroll
      for (int k = 0; k < 8; k++) acc[k] = fmaf(at, row[(k << 5) + lane], acc[k]);
    }
  }
#pragma unroll
  for (int o = 16; o; o >>= 1) asum += __shfl_xor_sync(0xffffffffu, asum, o);
  float inv = (end > beg) ? 1.f / asum : 0.f;
  float* X = g_X1 + (size_t)gw * 512;
  const float* ht = g_h1feat + (size_t)gw * 256;
#pragma unroll
  for (int k = 0; k < 8; k++) {
    X[(k << 5) + lane] = acc[k] * inv;
    X[256 + (k << 5) + lane] = ht[(k << 5) + lane];
  }
}

// ---------------- weight concat ----------------
__global__ void k_prepw(const float* __restrict__ ll, const float* __restrict__ lr,
                        float* __restrict__ W, int K2, int N) {
  int i = blockIdx.x * blockDim.x + threadIdx.x;
  int total = 2 * K2 * N;
  if (i >= total) return;
  int k = i / N, n = i % N;
  W[i] = (k < K2) ? ll[n * K2 + k] : lr[n * K2 + (k - K2)];
}

// ---------------- out prefill with bias ----------------
__global__ void k_fill_out(float* __restrict__ out, const float* __restrict__ outb) {
  int i = blockIdx.x * blockDim.x + threadIdx.x;
  if (i < cN2) out[i] = outb[0];
}

// ---------------- tf32 mma GEMM with 3-term compensation ----------------
__global__ __launch_bounds__(256, 2)
void k_gemm_tf32(const float* __restrict__ X, const float* __restrict__ W,
                 const float* __restrict__ bias, float* __restrict__ C,
                 int M, int K, int N, int do_relu,
                 const float* __restrict__ fw, float* __restrict__ fout) {
  __shared__ float As[128 * 36];
  __shared__ float Bs[32 * 72];
  int tid = threadIdx.x;
  int lane = tid & 31, w = tid >> 5;
  int wm = w >> 2, wn = w & 3;
  int r = lane >> 2, cb = lane & 3;
  int bm = blockIdx.y << 7, bn = blockIdx.x << 6;

  float acc[4][2][4];
#pragma unroll
  for (int mt = 0; mt < 4; mt++)
#pragma unroll
    for (int nt = 0; nt < 2; nt++)
#pragma unroll
      for (int j = 0; j < 4; j++) acc[mt][nt][j] = 0.f;

  for (int k0 = 0; k0 < K; k0 += 32) {
#pragma unroll
    for (int c = 0; c < 4; c++) {
      int idx = tid + (c << 8);
      int m = idx >> 3, kq = (idx & 7) << 2;
      float4 v = make_float4(0.f, 0.f, 0.f, 0.f);
      if (bm + m < M) v = *(const float4*)(X + (size_t)(bm + m) * K + k0 + kq);
      *(float4*)(As + m * 36 + kq) = v;
    }
#pragma unroll
    for (int c = 0; c < 2; c++) {
      int idx = tid + (c << 8);
      int k = idx >> 4, nq = (idx & 15) << 2;
      float4 v = *(const float4*)(W + (size_t)(k0 + k) * N + bn + nq);
      *(float4*)(Bs + k * 72 + nq) = v;
    }
    __syncthreads();
#pragma unroll
    for (int kk = 0; kk < 4; kk++) {
      uint32_t ah[4][4], al[4][4];
#pragma unroll
      for (int mt = 0; mt < 4; mt++) {
        const float* ap = As + (wm * 64 + mt * 16 + r) * 36 + kk * 8 + cb;
        float v0 = ap[0], v1 = ap[8 * 36], v2 = ap[4], v3 = ap[8 * 36 + 4];
        float h0 = tf32r(v0), h1 = tf32r(v1), h2 = tf32r(v2), h3 = tf32r(v3);
        ah[mt][0] = __float_as_uint(h0); al[mt][0] = __float_as_uint(tf32r(v0 - h0));
        ah[mt][1] = __float_as_uint(h1); al[mt][1] = __float_as_uint(tf32r(v1 - h1));
        ah[mt][2] = __float_as_uint(h2); al[mt][2] = __float_as_uint(tf32r(v2 - h2));
        ah[mt][3] = __float_as_uint(h3); al[mt][3] = __float_as_uint(tf32r(v3 - h3));
      }
      uint32_t bh[2][2], bl[2][2];
#pragma unroll
      for (int nt = 0; nt < 2; nt++) {
        const float* bp = Bs + (kk * 8 + cb) * 72 + wn * 16 + nt * 8 + r;
        float u0 = bp[0], u1 = bp[4 * 72];
        float h0 = tf32r(u0), h1 = tf32r(u1);
        bh[nt][0] = __float_as_uint(h0); bl[nt][0] = __float_as_uint(tf32r(u0 - h0));
        bh[nt][1] = __float_as_uint(h1); bl[nt][1] = __float_as_uint(tf32r(u1 - h1));
      }
#pragma unroll
      for (int mt = 0; mt < 4; mt++)
#pragma unroll
        for (int nt = 0; nt < 2; nt++) {
          mma_tf32(acc[mt][nt][0], acc[mt][nt][1], acc[mt][nt][2], acc[mt][nt][3],
                   ah[mt][0], ah[mt][1], ah[mt][2], ah[mt][3], bh[nt][0], bh[nt][1]);
          mma_tf32(acc[mt][nt][0], acc[mt][nt][1], acc[mt][nt][2], acc[mt][nt][3],
                   ah[mt][0], ah[mt][1], ah[mt][2], ah[mt][3], bl[nt][0], bl[nt][1]);
          mma_tf32(acc[mt][nt][0], acc[mt][nt][1], acc[mt][nt][2], acc[mt][nt][3],
                   al[mt][0], al[mt][1], al[mt][2], al[mt][3], bh[nt][0], bh[nt][1]);
        }
    }
    __syncthreads();
  }
#pragma unroll
  for (int mt = 0; mt < 4; mt++) {
    int row0 = bm + wm * 64 + mt * 16 + r;
    float p0 = 0.f, p1 = 0.f;
#pragma unroll
    for (int nt = 0; nt < 2; nt++) {
      int col = bn + wn * 16 + nt * 8 + 2 * cb;
      float2 bs = *(const float2*)(bias + col);
      float v0 = acc[mt][nt][0] + bs.x;
      float v1 = acc[mt][nt][1] + bs.y;
      float v2 = acc[mt][nt][2] + bs.x;
      float v3 = acc[mt][nt][3] + bs.y;
      if (do_relu) {
        v0 = fmaxf(v0, 0.f); v1 = fmaxf(v1, 0.f);
        v2 = fmaxf(v2, 0.f); v3 = fmaxf(v3, 0.f);
      }
      if (fw == nullptr) {
        if (row0 < M) *(float2*)(C + (size_t)row0 * N + col) = make_float2(v0, v1);
        if (row0 + 8 < M) *(float2*)(C + (size_t)(row0 + 8) * N + col) = make_float2(v2, v3);
      } else {
        float2 ow = *(const float2*)(fw + col);
        p0 += v0 * ow.x + v1 * ow.y;
        p1 += v2 * ow.x + v3 * ow.y;
      }
    }
    if (fw != nullptr) {
      p0 += __shfl_xor_sync(0xffffffffu, p0, 1);
      p0 += __shfl_xor_sync(0xffffffffu, p0, 2);
      p1 += __shfl_xor_sync(0xffffffffu, p1, 1);
      p1 += __shfl_xor_sync(0xffffffffu, p1, 2);
      if (cb == 0) {
        if (row0 < M) atomicAdd(fout + row0, p0);
        if (row0 + 8 < M) atomicAdd(fout + row0 + 8, p1);
      }
    }
  }
}

extern "C" void kernel_launch(void* const* d_in, const int* in_sizes, int n_in,
                              void* d_out, int out_size) {
  const int*   x    = (const int*)d_in[0];
  const float* xu   = (const float*)d_in[1];
  const int*   src0 = (const int*)d_in[2];
  const int*   dst0 = (const int*)d_in[3];
  const int*   src1 = (const int*)d_in[4];
  const int*   dst1 = (const int*)d_in[5];
  const float* tab  = (const float*)d_in[6];
  const float* lng  = (const float*)d_in[7];
  const float* lnb  = (const float*)d_in[8];
  const float* lpw1 = (const float*)d_in[9];
  const float* lpb1 = (const float*)d_in[10];
  const float* lpg  = (const float*)d_in[11];
  const float* lpbn = (const float*)d_in[12];
  const float* lpw2 = (const float*)d_in[13];
  const float* lpb2 = (const float*)d_in[14];
  const float* llw0 = (const float*)d_in[15];
  const float* llb0 = (const float*)d_in[16];
  const float* lrw0 = (const float*)d_in[17];
  const float* llw1 = (const float*)d_in[18];
  const float* llb1 = (const float*)d_in[19];
  const float* lrw1 = (const float*)d_in[20];
  const float* outw = (const float*)d_in[21];
  const float* outb = (const float*)d_in[22];
  float* out = (float*)d_out;

  float *p_un0, *p_X0, *p_X1, *p_W0, *p_W1, *p_h1, *p_A, *p_A1;
  int *p_deg, *p_rp, *p_cur, *p_ei, *p_deg1, *p_rp1, *p_cur1, *p_ei1;
  cudaGetSymbolAddress((void**)&p_un0, g_un0);
  cudaGetSymbolAddress((void**)&p_X0, g_X0);
  cudaGetSymbolAddress((void**)&p_X1, g_X1);
  cudaGetSymbolAddress((void**)&p_W0, g_W0);
  cudaGetSymbolAddress((void**)&p_W1, g_W1);
  cudaGetSymbolAddress((void**)&p_h1, g_h1feat);
  cudaGetSymbolAddress((void**)&p_A, g_A);
  cudaGetSymbolAddress((void**)&p_A1, g_A1);
  cudaGetSymbolAddress((void**)&p_deg, g_deg);
  cudaGetSymbolAddress((void**)&p_rp, g_rowptr);
  cudaGetSymbolAddress((void**)&p_cur, g_cursor);
  cudaGetSymbolAddress((void**)&p_ei, g_eidx);
  cudaGetSymbolAddress((void**)&p_deg1, g_deg1);
  cudaGetSymbolAddress((void**)&p_rp1, g_rowptr1);
  cudaGetSymbolAddress((void**)&p_cur1, g_cursor1);
  cudaGetSymbolAddress((void**)&p_ei1, g_eidx1);

  const int LP_SMEM = (6656 + 512 + 6656) * 4;  // 55296 B
  cudaFuncSetAttribute(k_edge_lp, cudaFuncAttributeMaxDynamicSharedMemorySize, LP_SMEM);

  // Streams/events created ONCE and cached (per-call creation trips the alloc guard).
  static cudaStream_t s1 = nullptr, s2 = nullptr, s3 = nullptr;
  static cudaEvent_t evRoot = nullptr, evB = nullptr, evC = nullptr, evD = nullptr,
                     evA0 = nullptr, evG0 = nullptr, evLP0 = nullptr, evU = nullptr,
                     evLP1 = nullptr;
  if (s1 == nullptr) {
    cudaStreamCreateWithFlags(&s1, cudaStreamNonBlocking);
    cudaStreamCreateWithFlags(&s2, cudaStreamNonBlocking);
    cudaStreamCreateWithFlags(&s3, cudaStreamNonBlocking);
    cudaEventCreateWithFlags(&evRoot, cudaEventDisableTiming);
    cudaEventCreateWithFlags(&evB, cudaEventDisableTiming);
    cudaEventCreateWithFlags(&evC, cudaEventDisableTiming);
    cudaEventCreateWithFlags(&evD, cudaEventDisableTiming);
    cudaEventCreateWithFlags(&evA0, cudaEventDisableTiming);
    cudaEventCreateWithFlags(&evG0, cudaEventDisableTiming);
    cudaEventCreateWithFlags(&evLP0, cudaEventDisableTiming);
    cudaEventCreateWithFlags(&evU, cudaEventDisableTiming);
    cudaEventCreateWithFlags(&evLP1, cudaEventDisableTiming);
  }

  // ---- fork ----
  cudaEventRecord(evRoot, 0);
  cudaStreamWaitEvent(s1, evRoot, 0);
  cudaStreamWaitEvent(s2, evRoot, 0);
  cudaStreamWaitEvent(s3, evRoot, 0);

  // Branch B (s1): L0 CSR build, then un0 (fp32-exact, off critical path)
  k_zero_deg<<<(cN1 + 255) / 256, 256, 0, s1>>>(p_deg, cN1);
  k_hist<<<(cE0 + 255) / 256, 256, 0, s1>>>(dst0, p_deg, cE0);
  k_scan<<<1, 1024, 0, s1>>>(p_deg, p_rp, p_cur, cN1, cE0);
  k_scatter<<<(cE0 + 255) / 256, 256, 0, s1>>>(dst0, p_cur, p_ei, cE0);
  cudaEventRecord(evB, s1);
  k_aggu<<<(cN1 * 32 + 255) / 256, 256, 0, s1>>>(src0, p_rp, p_ei, xu);
  cudaEventRecord(evU, s1);

  // Branch E (s2): edge_lp0 directly on xu, then prepw/fill
  k_edge_lp<<<296, 256, LP_SMEM, s2>>>(src0, dst0, cE0,
                                       xu, cU, 0, xu, cU, 0,
                                       lpw1, lpb1, lpg, lpbn, lpw2, lpb2, p_A);
  cudaEventRecord(evLP0, s2);
  k_prepw<<<(2 * 128 * 256 + 255) / 256, 256, 0, s2>>>(llw0, lrw0, p_W0, 128, 256);
  k_prepw<<<(2 * 256 * 256 + 255) / 256, 256, 0, s2>>>(llw1, lrw1, p_W1, 256, 256);
  k_fill_out<<<(cN2 + 255) / 256, 256, 0, s2>>>(out, outb);
  cudaEventRecord(evC, s2);

  // Branch D (s3): L1 CSR build, then edge_lp1 (needs un0 only; writes g_A1)
  k_zero_deg<<<(cN2 + 255) / 256, 256, 0, s3>>>(p_deg1, cN2);
  k_hist<<<(cE1 + 255) / 256, 256, 0, s3>>>(dst1, p_deg1, cE1);
  k_scan<<<1, 1024, 0, s3>>>(p_deg1, p_rp1, p_cur1, cN2, cE1);
  k_scatter<<<(cE1 + 255) / 256, 256, 0, s3>>>(dst1, p_cur1, p_ei1, cE1);
  cudaEventRecord(evD, s3);
  cudaStreamWaitEvent(s3, evU, 0);
  k_edge_lp<<<296, 256, LP_SMEM, s3>>>(src1, dst1, cE1,
                                       p_un0, 32, 0, p_un0, 32, 0,
                                       lpw1, lpb1, lpg, lpbn, lpw2, lpb2, p_A1);
  cudaEventRecord(evLP1, s3);

  // Main chain: embed, then agg0 (feat only)
  k_embed<<<(cN0 * 32 + 255) / 256, 256>>>(x, xu, tab, lng, lnb);
  cudaStreamWaitEvent(0, evLP0, 0);
  cudaStreamWaitEvent(0, evB, 0);
  k_agg0<<<(cN1 * 32 + 255) / 256, 256>>>(src0, p_rp, p_ei);
  cudaEventRecord(evA0, 0);

  // gemm0 on s1 (needs X0 + W0)
  cudaStreamWaitEvent(s1, evA0, 0);
  cudaStreamWaitEvent(s1, evC, 0);
  {
    dim3 grid(256 / 64, (cN1 + 127) / 128);
    k_gemm_tf32<<<grid, 256, 0, s1>>>(p_X0, p_W0, llb0, p_h1, cN1, 256, 256, 1,
                                      nullptr, nullptr);
  }
  cudaEventRecord(evG0, s1);

  // Tail on main: agg1 (needs h1feat + A1 + CSR1), then fused gemm1
  cudaStreamWaitEvent(0, evG0, 0);
  cudaStreamWaitEvent(0, evLP1, 0);
  cudaStreamWaitEvent(0, evD, 0);
  k_agg1<<<(cN2 * 32 + 255) / 256, 256>>>(src1, p_rp1, p_ei1, p_A1);
  {
    dim3 grid(256 / 64, (cN2 + 127) / 128);
    k_gemm_tf32<<<grid, 256>>>(p_X1, p_W1, llb1, nullptr, cN2, 512, 256, 0, outw, out);
  }
}

// round 17
// speedup vs baseline: 1.1218x; 1.1218x over previous
#include <cuda_runtime.h>
#include <cuda_bf16.h>
#include <cstdint>

#define cN0 200000
#define cN1 50000
#define cN2 10000
#define cL  10
#define cE0 800000
#define cE1 160000
#define cIN 128
#define cU  32
#define cLP 128

// ---------------- scratch (device globals; no runtime allocation) ----------------
__device__ float g_h0[(size_t)cN0 * 160];
__device__ __nv_bfloat16 g_h0b[(size_t)cN0 * 160];
__device__ float g_h1feat[(size_t)cN1 * 256];
__device__ float g_un0[(size_t)cN1 * 32];
__device__ float g_X0[(size_t)cN1 * 256];
__device__ float g_X1[(size_t)cN2 * 512];
__device__ float g_A[cE0];
// L0 CSR
__device__ int   g_eidx[cE0];
__device__ int   g_rowptr[cN1 + 1];
__device__ int   g_deg[cN1];
__device__ int   g_cursor[cN1];
// L1 CSR
__device__ int   g_eidx1[cE1];
__device__ int   g_rowptr1[cN2 + 1];
__device__ int   g_deg1[cN2];
__device__ int   g_cursor1[cN2];
__device__ float g_W0[256 * 256];
__device__ float g_W1[512 * 256];

__device__ __forceinline__ float tf32r(float x) {
  uint32_t u;
  asm("cvt.rna.tf32.f32 %0, %1;" : "=r"(u) : "f"(x));
  return __uint_as_float(u);
}
__device__ __forceinline__ void mma_tf32(float& d0, float& d1, float& d2, float& d3,
                                         uint32_t a0, uint32_t a1, uint32_t a2, uint32_t a3,
                                         uint32_t b0, uint32_t b1) {
  asm volatile(
      "mma.sync.aligned.m16n8k8.row.col.f32.tf32.tf32.f32 "
      "{%0,%1,%2,%3}, {%4,%5,%6,%7}, {%8,%9}, {%0,%1,%2,%3};"
      : "+f"(d0), "+f"(d1), "+f"(d2), "+f"(d3)
      : "r"(a0), "r"(a1), "r"(a2), "r"(a3), "r"(b0), "r"(b1));
}
__device__ __forceinline__ void mma_bf16(float& d0, float& d1, float& d2, float& d3,
                                         uint32_t a0, uint32_t a1, uint32_t a2, uint32_t a3,
                                         uint32_t b0, uint32_t b1) {
  asm volatile(
      "mma.sync.aligned.m16n8k16.row.col.f32.bf16.bf16.f32 "
      "{%0,%1,%2,%3}, {%4,%5,%6,%7}, {%8,%9}, {%0,%1,%2,%3};"
      : "+f"(d0), "+f"(d1), "+f"(d2), "+f"(d3)
      : "r"(a0), "r"(a1), "r"(a2), "r"(a3), "r"(b0), "r"(b1));
}
__device__ __forceinline__ uint32_t pack_bf16(float lo, float hi) {
  __nv_bfloat162 p = __float22bfloat162_rn(make_float2(lo, hi));
  return *reinterpret_cast<uint32_t*>(&p);
}
__device__ __forceinline__ float2 bf2f(uint32_t u) {
  return __bfloat1622float2(*reinterpret_cast<__nv_bfloat162*>(&u));
}

// ---------------- embedding bag + LN + relu + bf16 shadow (warp per node) ----------------
__global__ void k_embed(const int* __restrict__ x, const float* __restrict__ xu,
                        const float* __restrict__ tab, const float* __restrict__ g,
                        const float* __restrict__ b) {
  int n = (blockIdx.x * blockDim.x + threadIdx.x) >> 5;
  int lane = threadIdx.x & 31;
  if (n >= cN0) return;
  const int* xr = x + (size_t)n * cL;
  float4 v = make_float4(0.f, 0.f, 0.f, 0.f);
#pragma unroll
  for (int l = 0; l < cL; l++) {
    int id = xr[l];
    if (id != 0) {
      float4 t = ((const float4*)(tab + (size_t)id * cIN))[lane];
      v.x += t.x; v.y += t.y; v.z += t.z; v.w += t.w;
    }
  }
  float s = v.x + v.y + v.z + v.w;
  float q = v.x * v.x + v.y * v.y + v.z * v.z + v.w * v.w;
#pragma unroll
  for (int o = 16; o; o >>= 1) {
    s += __shfl_xor_sync(0xffffffffu, s, o);
    q += __shfl_xor_sync(0xffffffffu, q, o);
  }
  float m = s * (1.f / cIN);
  float rs = rsqrtf(q * (1.f / cIN) - m * m + 1e-5f);
  float4 gv = ((const float4*)g)[lane];
  float4 bv = ((const float4*)b)[lane];
  float4 ov;
  ov.x = fmaxf((v.x - m) * rs * gv.x + bv.x, 0.f);
  ov.y = fmaxf((v.y - m) * rs * gv.y + bv.y, 0.f);
  ov.z = fmaxf((v.z - m) * rs * gv.z + bv.z, 0.f);
  ov.w = fmaxf((v.w - m) * rs * gv.w + bv.w, 0.f);
  if (n < cN1) ((float4*)(g_h0 + (size_t)n * 160))[lane] = ov;  // fp32 feat, targets only
  float xv = xu[(size_t)n * cU + lane];
  // bf16 shadow (all nodes; neighbor gathers).
  __nv_bfloat16* rb = g_h0b + (size_t)n * 160;
  uint2 pk;
  pk.x = pack_bf16(ov.x, ov.y);
  pk.y = pack_bf16(ov.z, ov.w);
  ((uint2*)rb)[lane] = pk;
  rb[cIN + lane] = __float2bfloat16(xv);
}

// ---------------- CSR build ----------------
__global__ void k_zero_deg(int* __restrict__ deg, int n) {
  int i = blockIdx.x * blockDim.x + threadIdx.x;
  if (i < n) deg[i] = 0;
}
__global__ void k_hist(const int* __restrict__ dst, int* __restrict__ deg, int E) {
  int i = blockIdx.x * blockDim.x + threadIdx.x;
  if (i < E) atomicAdd(&deg[dst[i]], 1);
}
__global__ void k_scan(int* __restrict__ deg, int* __restrict__ rowptr,
                       int* __restrict__ cursor, int n, int E) {
  __shared__ int sh[1024];
  int t = threadIdx.x;
  int chunk = (n + 1023) / 1024;
  int beg = t * chunk;
  int end = beg + chunk; if (end > n) end = n; if (beg > n) beg = n;
  int local = 0;
  for (int i = beg; i < end; i++) local += deg[i];
  sh[t] = local;
  __syncthreads();
  for (int off = 1; off < 1024; off <<= 1) {
    int v = (t >= off) ? sh[t - off] : 0;
    __syncthreads();
    sh[t] += v;
    __syncthreads();
  }
  int offset = (t == 0) ? 0 : sh[t - 1];
  for (int i = beg; i < end; i++) {
    rowptr[i] = offset;
    cursor[i] = offset;
    offset += deg[i];
  }
  if (t == 0) rowptr[n] = E;
}
__global__ void k_scatter(const int* __restrict__ dst, int* __restrict__ cursor,
                          int* __restrict__ eidx, int E) {
  int i = blockIdx.x * blockDim.x + threadIdx.x;
  if (i < E) {
    int pos = atomicAdd(&cursor[dst[i]], 1);
    eidx[pos] = i;
  }
}

// ---------------- per-edge LP attention MLP via bf16 mma m16n8k16, single pass ----------
__global__ __launch_bounds__(256, 2)
void k_edge_lp(const int* __restrict__ src, const int* __restrict__ dst, int E,
               const float* __restrict__ usrc, int sstr, int soff,
               const float* __restrict__ utgt, int tstr, int toff,
               const float* __restrict__ w1, const float* __restrict__ b1,
               const float* __restrict__ lg, const float* __restrict__ lbn,
               const float* __restrict__ w2, const float* __restrict__ b2p) {
  extern __shared__ float sm[];
  uint32_t* w1b = (uint32_t*)sm;
  float4* pp = (float4*)(sm + 6656);
  uint32_t* hstage = (uint32_t*)(sm + 6656 + 512);

  for (int i = threadIdx.x; i < 128 * 48; i += blockDim.x) {
    int o = i / 48, j = i % 48;
    w1b[o * 52 + j] = pack_bf16(w1[o * 96 + 2 * j], w1[o * 96 + 2 * j + 1]);
  }
  for (int i = threadIdx.x; i < 128; i += blockDim.x)
    pp[i] = make_float4(lg[i], lbn[i], w2[i], b1[i]);
  __syncthreads();

  int lane = threadIdx.x & 31;
  int w = threadIdx.x >> 5;
  int gid = lane >> 2;
  int tig = lane & 3;
  uint32_t* myh = hstage + w * (16 * 52);
  float b2v = b2p[0];
  int warps_tot = gridDim.x * (blockDim.x >> 5);

  for (long base = ((long)blockIdx.x * (blockDim.x >> 5) + w) * 16; base < E;
       base += (long)warps_tot * 16) {
#pragma unroll
    for (int t = 0; t < 16; t++) {
      long ee = base + t;
      int e = (ee < E) ? (int)ee : (E - 1);
      int sn = src[e], dn = dst[e];
      float uj = usrc[(size_t)sn * sstr + soff + lane];
      float ui = utgt[(size_t)dn * tstr + toff + lane];
      float v0 = fabsf(ui - uj);
      float v1 = ui + uj;
      float v2 = ui * uj;
      float n0 = __shfl_down_sync(0xffffffffu, v0, 1);
      float n1 = __shfl_down_sync(0xffffffffu, v1, 1);
      float n2 = __shfl_down_sync(0xffffffffu, v2, 1);
      if ((lane & 1) == 0) {
        int j = lane >> 1;
        uint32_t* row = myh + t * 52;
        row[j]      = pack_bf16(v0, n0);
        row[16 + j] = pack_bf16(v1, n1);
        row[32 + j] = pack_bf16(v2, n2);
      }
    }
    __syncwarp();

    uint32_t A[6][4];
#pragma unroll
    for (int kk = 0; kk < 6; kk++) {
      int ko = kk * 8 + tig;
      A[kk][0] = myh[gid * 52 + ko];
      A[kk][1] = myh[(gid + 8) * 52 + ko];
      A[kk][2] = myh[gid * 52 + ko + 4];
      A[kk][3] = myh[(gid + 8) * 52 + ko + 4];
    }

    float acc[16][4];
    float S0 = 0.f, Q0 = 0.f, S1 = 0.f, Q1 = 0.f;
#pragma unroll
    for (int nn = 0; nn < 16; nn++) {
      float d0 = 0.f, d1 = 0.f, d2 = 0.f, d3 = 0.f;
      const uint32_t* wrow = w1b + (nn * 8 + gid) * 52 + tig;
#pragma unroll
      for (int kk = 0; kk < 6; kk++) {
        uint32_t b0 = wrow[kk * 8];
        uint32_t b1r = wrow[kk * 8 + 4];
        mma_bf16(d0, d1, d2, d3, A[kk][0], A[kk][1], A[kk][2], A[kk][3], b0, b1r);
      }
      float4 p0 = pp[nn * 8 + 2 * tig];
      float4 p1 = pp[nn * 8 + 2 * tig + 1];
      d0 += p0.w; d1 += p1.w; d2 += p0.w; d3 += p1.w;
      acc[nn][0] = d0; acc[nn][1] = d1; acc[nn][2] = d2; acc[nn][3] = d3;
      S0 += d0 + d1; Q0 += d0 * d0 + d1 * d1;
      S1 += d2 + d3; Q1 += d2 * d2 + d3 * d3;
    }
#pragma unroll
    for (int o = 1; o <= 2; o <<= 1) {
      S0 += __shfl_xor_sync(0xffffffffu, S0, o);
      Q0 += __shfl_xor_sync(0xffffffffu, Q0, o);
      S1 += __shfl_xor_sync(0xffffffffu, S1, o);
      Q1 += __shfl_xor_sync(0xffffffffu, Q1, o);
    }
    float m0 = S0 * (1.f / 128.f);
    float rs0 = rsqrtf(Q0 * (1.f / 128.f) - m0 * m0 + 1e-5f);
    float m1 = S1 * (1.f / 128.f);
    float rs1 = rsqrtf(Q1 * (1.f / 128.f) - m1 * m1 + 1e-5f);

    float P0 = 0.f, P1 = 0.f;
#pragma unroll
    for (int nn = 0; nn < 16; nn++) {
      float4 p0 = pp[nn * 8 + 2 * tig];
      float4 p1 = pp[nn * 8 + 2 * tig + 1];
      P0 += fmaxf((acc[nn][0] - m0) * rs0 * p0.x + p0.y, 0.f) * p0.z;
      P0 += fmaxf((acc[nn][1] - m0) * rs0 * p1.x + p1.y, 0.f) * p1.z;
      P1 += fmaxf((acc[nn][2] - m1) * rs1 * p0.x + p0.y, 0.f) * p0.z;
      P1 += fmaxf((acc[nn][3] - m1) * rs1 * p1.x + p1.y, 0.f) * p1.z;
    }
#pragma unroll
    for (int o = 1; o <= 2; o <<= 1) {
      P0 += __shfl_xor_sync(0xffffffffu, P0, o);
      P1 += __shfl_xor_sync(0xffffffffu, P1, o);
    }
    if (tig == 0) {
      if (base + gid < E)
        g_A[base + gid] = 1.f / (1.f + expf(-(P0 + b2v)));
      if (base + gid + 8 < E)
        g_A[base + gid + 8] = 1.f / (1.f + expf(-(P1 + b2v)));
    }
    __syncwarp();
  }
}

// ---------------- gather aggregation, unroll-2 prefetch -------
__global__ void k_agg0(const int* __restrict__ src, const int* __restrict__ rowptr,
                       const int* __restrict__ eidx) {
  int gw = (blockIdx.x * blockDim.x + threadIdx.x) >> 5;
  int lane = threadIdx.x & 31;
  if (gw >= cN1) return;
  int beg = rowptr[gw], end = rowptr[gw + 1];
  float a0 = 0.f, a1 = 0.f, a2 = 0.f, a3 = 0.f, au0 = 0.f, au1 = 0.f;
  float asum = 0.f;
  for (int chunk = beg; chunk < end; chunk += 32) {
    int n = end - chunk; if (n > 32) n = 32;
    int myi = chunk + lane;
    int e = (myi < end) ? eidx[myi] : 0;
    int s = (myi < end) ? src[e] : 0;
    float a = (myi < end) ? g_A[e] : 0.f;
    asum += a;
    int t = 0;
    for (; t + 1 < n; t += 2) {
      int sA = __shfl_sync(0xffffffffu, s, t);
      int sB = __shfl_sync(0xffffffffu, s, t + 1);
      float aA = __shfl_sync(0xffffffffu, a, t);
      float aB = __shfl_sync(0xffffffffu, a, t + 1);
      const uint32_t* rA = (const uint32_t*)(g_h0b + (size_t)sA * 160);
      const uint32_t* rB = (const uint32_t*)(g_h0b + (size_t)sB * 160);
      uint32_t wA0 = rA[lane], wA1 = rA[32 + lane], wAu = rA[64 + (lane & 15)];
      uint32_t wB0 = rB[lane], wB1 = rB[32 + lane], wBu = rB[64 + (lane & 15)];
      float2 fA0 = bf2f(wA0), fA1 = bf2f(wA1), fAu = bf2f(wAu);
      a0 = fmaf(aA, fA0.x, a0); a1 = fmaf(aA, fA0.y, a1);
      a2 = fmaf(aA, fA1.x, a2); a3 = fmaf(aA, fA1.y, a3);
      au0 += fAu.x; au1 += fAu.y;
      float2 fB0 = bf2f(wB0), fB1 = bf2f(wB1), fBu = bf2f(wBu);
      a0 = fmaf(aB, fB0.x, a0); a1 = fmaf(aB, fB0.y, a1);
      a2 = fmaf(aB, fB1.x, a2); a3 = fmaf(aB, fB1.y, a3);
      au0 += fBu.x; au1 += fBu.y;
    }
    if (t < n) {
      int st = __shfl_sync(0xffffffffu, s, t);
      float at = __shfl_sync(0xffffffffu, a, t);
      const uint32_t* rp = (const uint32_t*)(g_h0b + (size_t)st * 160);
      float2 f0 = bf2f(rp[lane]);
      float2 f1 = bf2f(rp[32 + lane]);
      a0 = fmaf(at, f0.x, a0); a1 = fmaf(at, f0.y, a1);
      a2 = fmaf(at, f1.x, a2); a3 = fmaf(at, f1.y, a3);
      float2 fu = bf2f(rp[64 + (lane & 15)]);
      au0 += fu.x; au1 += fu.y;
    }
  }
#pragma unroll
  for (int o = 16; o; o >>= 1) asum += __shfl_xor_sync(0xffffffffu, asum, o);
  float inv = (end > beg) ? 1.f / asum : 0.f;
  a0 *= inv; a1 *= inv; a2 *= inv; a3 *= inv;
  float* X = g_X0 + (size_t)gw * 256;
  *(float2*)(X + 2 * lane) = make_float2(a0, a1);
  *(float2*)(X + 64 + 2 * lane) = make_float2(a2, a3);
  const float* ht = g_h0 + (size_t)gw * 160;
  X[128 + lane] = ht[lane];
  X[160 + lane] = ht[32 + lane];
  X[192 + lane] = ht[64 + lane];
  X[224 + lane] = ht[96 + lane];
  if (lane < 16)
    *(float2*)(g_un0 + (size_t)gw * 32 + 2 * lane) = make_float2(au0, au1);
}

__global__ void k_agg1(const int* __restrict__ src, const int* __restrict__ rowptr,
                       const int* __restrict__ eidx) {
  int gw = (blockIdx.x * blockDim.x + threadIdx.x) >> 5;
  int lane = threadIdx.x & 31;
  if (gw >= cN2) return;
  int beg = rowptr[gw], end = rowptr[gw + 1];
  float acc[8] = {0.f, 0.f, 0.f, 0.f, 0.f, 0.f, 0.f, 0.f};
  float asum = 0.f;
  for (int chunk = beg; chunk < end; chunk += 32) {
    int n = end - chunk; if (n > 32) n = 32;
    int myi = chunk + lane;
    int e = (myi < end) ? eidx[myi] : 0;
    int s = (myi < end) ? src[e] : 0;
    float a = (myi < end) ? g_A[e] : 0.f;
    asum += a;
    int t = 0;
    for (; t + 1 < n; t += 2) {
      int sA = __shfl_sync(0xffffffffu, s, t);
      int sB = __shfl_sync(0xffffffffu, s, t + 1);
      float aA = __shfl_sync(0xffffffffu, a, t);
      float aB = __shfl_sync(0xffffffffu, a, t + 1);
      const float* rA = g_h1feat + (size_t)sA * 256;
      const float* rB = g_h1feat + (size_t)sB * 256;
      float vA[8], vB[8];
#pragma unroll
      for (int k = 0; k < 8; k++) vA[k] = rA[(k << 5) + lane];
#pragma unroll
      for (int k = 0; k < 8; k++) vB[k] = rB[(k << 5) + lane];
#pragma unroll
      for (int k = 0; k < 8; k++) acc[k] = fmaf(aA, vA[k], acc[k]);
#pragma unroll
      for (int k = 0; k < 8; k++) acc[k] = fmaf(aB, vB[k], acc[k]);
    }
    if (t < n) {
      int st = __shfl_sync(0xffffffffu, s, t);
      float at = __shfl_sync(0xffffffffu, a, t);
      const float* row = g_h1feat + (size_t)st * 256;
#pragma unroll
      for (int k = 0; k < 8; k++) acc[k] = fmaf(at, row[(k << 5) + lane], acc[k]);
    }
  }
#pragma unroll
  for (int o = 16; o; o >>= 1) asum += __shfl_xor_sync(0xffffffffu, asum, o);
  float inv = (end > beg) ? 1.f / asum : 0.f;
  float* X = g_X1 + (size_t)gw * 512;
  const float* ht = g_h1feat + (size_t)gw * 256;
#pragma unroll
  for (int k = 0; k < 8; k++) {
    X[(k << 5) + lane] = acc[k] * inv;
    X[256 + (k << 5) + lane] = ht[(k << 5) + lane];
  }
}

// ---------------- weight concat ----------------
__global__ void k_prepw(const float* __restrict__ ll, const float* __restrict__ lr,
                        float* __restrict__ W, int K2, int N) {
  int i = blockIdx.x * blockDim.x + threadIdx.x;
  int total = 2 * K2 * N;
  if (i >= total) return;
  int k = i / N, n = i % N;
  W[i] = (k < K2) ? ll[n * K2 + k] : lr[n * K2 + (k - K2)];
}

// ---------------- out prefill with bias ----------------
__global__ void k_fill_out(float* __restrict__ out, const float* __restrict__ outb) {
  int i = blockIdx.x * blockDim.x + threadIdx.x;
  if (i < cN2) out[i] = outb[0];
}

// ---------------- tf32 mma GEMM with 3-term compensation ----------------
__global__ __launch_bounds__(256, 2)
void k_gemm_tf32(const float* __restrict__ X, const float* __restrict__ W,
                 const float* __restrict__ bias, float* __restrict__ C,
                 int M, int K, int N, int do_relu,
                 const float* __restrict__ fw, float* __restrict__ fout) {
  __shared__ float As[128 * 36];
  __shared__ float Bs[32 * 72];
  int tid = threadIdx.x;
  int lane = tid & 31, w = tid >> 5;
  int wm = w >> 2, wn = w & 3;
  int r = lane >> 2, cb = lane & 3;
  int bm = blockIdx.y << 7, bn = blockIdx.x << 6;

  float acc[4][2][4];
#pragma unroll
  for (int mt = 0; mt < 4; mt++)
#pragma unroll
    for (int nt = 0; nt < 2; nt++)
#pragma unroll
      for (int j = 0; j < 4; j++) acc[mt][nt][j] = 0.f;

  for (int k0 = 0; k0 < K; k0 += 32) {
#pragma unroll
    for (int c = 0; c < 4; c++) {
      int idx = tid + (c << 8);
      int m = idx >> 3, kq = (idx & 7) << 2;
      float4 v = make_float4(0.f, 0.f, 0.f, 0.f);
      if (bm + m < M) v = *(const float4*)(X + (size_t)(bm + m) * K + k0 + kq);
      *(float4*)(As + m * 36 + kq) = v;
    }
#pragma unroll
    for (int c = 0; c < 2; c++) {
      int idx = tid + (c << 8);
      int k = idx >> 4, nq = (idx & 15) << 2;
      float4 v = *(const float4*)(W + (size_t)(k0 + k) * N + bn + nq);
      *(float4*)(Bs + k * 72 + nq) = v;
    }
    __syncthreads();
#pragma unroll
    for (int kk = 0; kk < 4; kk++) {
      uint32_t ah[4][4], al[4][4];
#pragma unroll
      for (int mt = 0; mt < 4; mt++) {
        const float* ap = As + (wm * 64 + mt * 16 + r) * 36 + kk * 8 + cb;
        float v0 = ap[0], v1 = ap[8 * 36], v2 = ap[4], v3 = ap[8 * 36 + 4];
        float h0 = tf32r(v0), h1 = tf32r(v1), h2 = tf32r(v2), h3 = tf32r(v3);
        ah[mt][0] = __float_as_uint(h0); al[mt][0] = __float_as_uint(tf32r(v0 - h0));
        ah[mt][1] = __float_as_uint(h1); al[mt][1] = __float_as_uint(tf32r(v1 - h1));
        ah[mt][2] = __float_as_uint(h2); al[mt][2] = __float_as_uint(tf32r(v2 - h2));
        ah[mt][3] = __float_as_uint(h3); al[mt][3] = __float_as_uint(tf32r(v3 - h3));
      }
      uint32_t bh[2][2], bl[2][2];
#pragma unroll
      for (int nt = 0; nt < 2; nt++) {
        const float* bp = Bs + (kk * 8 + cb) * 72 + wn * 16 + nt * 8 + r;
        float u0 = bp[0], u1 = bp[4 * 72];
        float h0 = tf32r(u0), h1 = tf32r(u1);
        bh[nt][0] = __float_as_uint(h0); bl[nt][0] = __float_as_uint(tf32r(u0 - h0));
        bh[nt][1] = __float_as_uint(h1); bl[nt][1] = __float_as_uint(tf32r(u1 - h1));
      }
#pragma unroll
      for (int mt = 0; mt < 4; mt++)
#pragma unroll
        for (int nt = 0; nt < 2; nt++) {
          mma_tf32(acc[mt][nt][0], acc[mt][nt][1], acc[mt][nt][2], acc[mt][nt][3],
                   ah[mt][0], ah[mt][1], ah[mt][2], ah[mt][3], bh[nt][0], bh[nt][1]);
          mma_tf32(acc[mt][nt][0], acc[mt][nt][1], acc[mt][nt][2], acc[mt][nt][3],
                   ah[mt][0], ah[mt][1], ah[mt][2], ah[mt][3], bl[nt][0], bl[nt][1]);
          mma_tf32(acc[mt][nt][0], acc[mt][nt][1], acc[mt][nt][2], acc[mt][nt][3],
                   al[mt][0], al[mt][1], al[mt][2], al[mt][3], bh[nt][0], bh[nt][1]);
        }
    }
    __syncthreads();
  }
#pragma unroll
  for (int mt = 0; mt < 4; mt++) {
    int row0 = bm + wm * 64 + mt * 16 + r;
    float p0 = 0.f, p1 = 0.f;
#pragma unroll
    for (int nt = 0; nt < 2; nt++) {
      int col = bn + wn * 16 + nt * 8 + 2 * cb;
      float2 bs = *(const float2*)(bias + col);
      float v0 = acc[mt][nt][0] + bs.x;
      float v1 = acc[mt][nt][1] + bs.y;
      float v2 = acc[mt][nt][2] + bs.x;
      float v3 = acc[mt][nt][3] + bs.y;
      if (do_relu) {
        v0 = fmaxf(v0, 0.f); v1 = fmaxf(v1, 0.f);
        v2 = fmaxf(v2, 0.f); v3 = fmaxf(v3, 0.f);
      }
      if (fw == nullptr) {
        if (row0 < M) *(float2*)(C + (size_t)row0 * N + col) = make_float2(v0, v1);
        if (row0 + 8 < M) *(float2*)(C + (size_t)(row0 + 8) * N + col) = make_float2(v2, v3);
      } else {
        float2 ow = *(const float2*)(fw + col);
        p0 += v0 * ow.x + v1 * ow.y;
        p1 += v2 * ow.x + v3 * ow.y;
      }
    }
    if (fw != nullptr) {
      p0 += __shfl_xor_sync(0xffffffffu, p0, 1);
      p0 += __shfl_xor_sync(0xffffffffu, p0, 2);
      p1 += __shfl_xor_sync(0xffffffffu, p1, 1);
      p1 += __shfl_xor_sync(0xffffffffu, p1, 2);
      if (cb == 0) {
        if (row0 < M) atomicAdd(fout + row0, p0);
        if (row0 + 8 < M) atomicAdd(fout + row0 + 8, p1);
      }
    }
  }
}

extern "C" void kernel_launch(void* const* d_in, const int* in_sizes, int n_in,
                              void* d_out, int out_size) {
  const int*   x    = (const int*)d_in[0];
  const float* xu   = (const float*)d_in[1];
  const int*   src0 = (const int*)d_in[2];
  const int*   dst0 = (const int*)d_in[3];
  const int*   src1 = (const int*)d_in[4];
  const int*   dst1 = (const int*)d_in[5];
  const float* tab  = (const float*)d_in[6];
  const float* lng  = (const float*)d_in[7];
  const float* lnb  = (const float*)d_in[8];
  const float* lpw1 = (const float*)d_in[9];
  const float* lpb1 = (const float*)d_in[10];
  const float* lpg  = (const float*)d_in[11];
  const float* lpbn = (const float*)d_in[12];
  const float* lpw2 = (const float*)d_in[13];
  const float* lpb2 = (const float*)d_in[14];
  const float* llw0 = (const float*)d_in[15];
  const float* llb0 = (const float*)d_in[16];
  const float* lrw0 = (const float*)d_in[17];
  const float* llw1 = (const float*)d_in[18];
  const float* llb1 = (const float*)d_in[19];
  const float* lrw1 = (const float*)d_in[20];
  const float* outw = (const float*)d_in[21];
  const float* outb = (const float*)d_in[22];
  float* out = (float*)d_out;

  float *p_h0, *p_un0, *p_X0, *p_X1, *p_W0, *p_W1, *p_h1;
  int *p_deg, *p_rp, *p_cur, *p_ei, *p_deg1, *p_rp1, *p_cur1, *p_ei1;
  cudaGetSymbolAddress((void**)&p_h0, g_h0);
  cudaGetSymbolAddress((void**)&p_un0, g_un0);
  cudaGetSymbolAddress((void**)&p_X0, g_X0);
  cudaGetSymbolAddress((void**)&p_X1, g_X1);
  cudaGetSymbolAddress((void**)&p_W0, g_W0);
  cudaGetSymbolAddress((void**)&p_W1, g_W1);
  cudaGetSymbolAddress((void**)&p_h1, g_h1feat);
  cudaGetSymbolAddress((void**)&p_deg, g_deg);
  cudaGetSymbolAddress((void**)&p_rp, g_rowptr);
  cudaGetSymbolAddress((void**)&p_cur, g_cursor);
  cudaGetSymbolAddress((void**)&p_ei, g_eidx);
  cudaGetSymbolAddress((void**)&p_deg1, g_deg1);
  cudaGetSymbolAddress((void**)&p_rp1, g_rowptr1);
  cudaGetSymbolAddress((void**)&p_cur1, g_cursor1);
  cudaGetSymbolAddress((void**)&p_ei1, g_eidx1);

  const int LP_SMEM = (6656 + 512 + 6656) * 4;  // 55296 B
  cudaFuncSetAttribute(k_edge_lp, cudaFuncAttributeMaxDynamicSharedMemorySize, LP_SMEM);

  // Streams/events created ONCE and cached (per-call creation trips the alloc guard).
  static cudaStream_t s1 = nullptr, s2 = nullptr, s3 = nullptr;
  static cudaEvent_t evRoot = nullptr, evB = nullptr, evC = nullptr, evD = nullptr,
                     evA0 = nullptr, evG0 = nullptr, evLP0 = nullptr;
  if (s1 == nullptr) {
    cudaStreamCreateWithFlags(&s1, cudaStreamNonBlocking);
    cudaStreamCreateWithFlags(&s2, cudaStreamNonBlocking);
    cudaStreamCreateWithFlags(&s3, cudaStreamNonBlocking);
    cudaEventCreateWithFlags(&evRoot, cudaEventDisableTiming);
    cudaEventCreateWithFlags(&evB, cudaEventDisableTiming);
    cudaEventCreateWithFlags(&evC, cudaEventDisableTiming);
    cudaEventCreateWithFlags(&evD, cudaEventDisableTiming);
    cudaEventCreateWithFlags(&evA0, cudaEventDisableTiming);
    cudaEventCreateWithFlags(&evG0, cudaEventDisableTiming);
    cudaEventCreateWithFlags(&evLP0, cudaEventDisableTiming);
  }

  // ---- fork ----
  cudaEventRecord(evRoot, 0);
  cudaStreamWaitEvent(s1, evRoot, 0);
  cudaStreamWaitEvent(s2, evRoot, 0);
  cudaStreamWaitEvent(s3, evRoot, 0);

  // Branch B (s1): L0 CSR build
  k_zero_deg<<<(cN1 + 255) / 256, 256, 0, s1>>>(p_deg, cN1);
  k_hist<<<(cE0 + 255) / 256, 256, 0, s1>>>(dst0, p_deg, cE0);
  k_scan<<<1, 1024, 0, s1>>>(p_deg, p_rp, p_cur, cN1, cE0);
  k_scatter<<<(cE0 + 255) / 256, 256, 0, s1>>>(dst0, p_cur, p_ei, cE0);
  cudaEventRecord(evB, s1);

  // Branch E (s2): edge_lp0 DIRECTLY on xu (no dependency on embed), then prepw/fill
  k_edge_lp<<<296, 256, LP_SMEM, s2>>>(src0, dst0, cE0,
                                       xu, cU, 0, xu, cU, 0,
                                       lpw1, lpb1, lpg, lpbn, lpw2, lpb2);
  cudaEventRecord(evLP0, s2);
  k_prepw<<<(2 * 128 * 256 + 255) / 256, 256, 0, s2>>>(llw0, lrw0, p_W0, 128, 256);
  k_prepw<<<(2 * 256 * 256 + 255) / 256, 256, 0, s2>>>(llw1, lrw1, p_W1, 256, 256);
  k_fill_out<<<(cN2 + 255) / 256, 256, 0, s2>>>(out, outb);
  cudaEventRecord(evC, s2);

  // Branch D (s3): L1 CSR build
  k_zero_deg<<<(cN2 + 255) / 256, 256, 0, s3>>>(p_deg1, cN2);
  k_hist<<<(cE1 + 255) / 256, 256, 0, s3>>>(dst1, p_deg1, cE1);
  k_scan<<<1, 1024, 0, s3>>>(p_deg1, p_rp1, p_cur1, cN2, cE1);
  k_scatter<<<(cE1 + 255) / 256, 256, 0, s3>>>(dst1, p_cur1, p_ei1, cE1);
  cudaEventRecord(evD, s3);

  // Main chain: embed runs concurrent with edge_lp0
  k_embed<<<(cN0 * 32 + 255) / 256, 256>>>(x, xu, tab, lng, lnb);
  cudaStreamWaitEvent(0, evLP0, 0);
  cudaStreamWaitEvent(0, evB, 0);
  k_agg0<<<(cN1 * 32 + 255) / 256, 256>>>(src0, p_rp, p_ei);
  cudaEventRecord(evA0, 0);

  // gemm0 on s1 (needs X0 + W0), concurrent with edge_lp1 on main
  cudaStreamWaitEvent(s1, evA0, 0);
  cudaStreamWaitEvent(s1, evC, 0);
  {
    dim3 grid(256 / 64, (cN1 + 127) / 128);
    k_gemm_tf32<<<grid, 256, 0, s1>>>(p_X0, p_W0, llb0, p_h1, cN1, 256, 256, 1,
                                      nullptr, nullptr);
  }
  cudaEventRecord(evG0, s1);

  // edge_lp1 on main (needs un0 from agg0)
  k_edge_lp<<<296, 256, LP_SMEM>>>(src1, dst1, cE1,
                                   p_un0, 32, 0, p_un0, 32, 0,
                                   lpw1, lpb1, lpg, lpbn, lpw2, lpb2);
  cudaStreamWaitEvent(0, evG0, 0);
  cudaStreamWaitEvent(0, evD, 0);
  k_agg1<<<(cN2 * 32 + 255) / 256, 256>>>(src1, p_rp1, p_ei1);
  {
    dim3 grid(256 / 64, (cN2 + 127) / 128);
    k_gemm_tf32<<<grid, 256>>>(p_X1, p_W1, llb1, nullptr, cN2, 512, 256, 0, outw, out);
  }
}